// round 4
// baseline (speedup 1.0000x reference)
#include <cuda_runtime.h>
#include <cstdint>

#define D_DIM 64
#define BT 32            // b per block
#define NT 64            // n per block
#define TPB 256
#define XSTRIDE 68       // floats; 16B-aligned row stride, conflict-free
#define ASTRIDE 68

// ---- packed f32x2 helpers (Blackwell FFMA2 path) ----
__device__ __forceinline__ uint64_t pk2(float lo, float hi) {
    uint64_t r; asm("mov.b64 %0, {%1, %2};" : "=l"(r) : "f"(lo), "f"(hi)); return r;
}
__device__ __forceinline__ void upk2(uint64_t v, float& lo, float& hi) {
    asm("mov.b64 {%0, %1}, %2;" : "=f"(lo), "=f"(hi) : "l"(v));
}
__device__ __forceinline__ uint64_t fma2(uint64_t a, uint64_t b, uint64_t c) {
    uint64_t d; asm("fma.rn.f32x2 %0, %1, %2, %3;" : "=l"(d) : "l"(a), "l"(b), "l"(c)); return d;
}
__device__ __forceinline__ uint64_t mul2(uint64_t a, uint64_t b) {
    uint64_t d; asm("mul.rn.f32x2 %0, %1, %2;" : "=l"(d) : "l"(a), "l"(b)); return d;
}
__device__ __forceinline__ uint64_t add2(uint64_t a, uint64_t b) {
    uint64_t d; asm("add.rn.f32x2 %0, %1, %2;" : "=l"(d) : "l"(a), "l"(b)); return d;
}

extern __shared__ float smem_dyn[];

// One 4-dim block, 2 b x 4 n per thread. All 10 LDS.128 issued up front,
// then a pure 64-packed-fma burst.
__device__ __forceinline__ void do_dblk(const float* __restrict__ xrow,
                                        const float* __restrict__ arow,
                                        const float* __restrict__ brow,
                                        int dblk, uint64_t M1,
                                        uint64_t (&sacc)[2][2],
                                        uint64_t (&pacc)[2][2])
{
    // ---- stage: batch all shared loads ----
    float4 xv0 = *reinterpret_cast<const float4*>(xrow + dblk);
    float4 xv1 = *reinterpret_cast<const float4*>(xrow + XSTRIDE + dblk);
    uint64_t A[4][2], Bv[4][2];
    #pragma unroll
    for (int dd = 0; dd < 4; dd++) {
        const int off = (dblk + dd) * ASTRIDE;
        const ulonglong2 av = *reinterpret_cast<const ulonglong2*>(arow + off);
        const ulonglong2 bv = *reinterpret_cast<const ulonglong2*>(brow + off);
        A[dd][0] = av.x; A[dd][1] = av.y;
        Bv[dd][0] = bv.x; Bv[dd][1] = bv.y;
    }
    const float x0[4] = {xv0.x, xv0.y, xv0.z, xv0.w};
    const float x1[4] = {xv1.x, xv1.y, xv1.z, xv1.w};

    // ---- compute burst ----
    #pragma unroll
    for (int dd = 0; dd < 4; dd++) {
        const uint64_t xp0 = pk2(x0[dd], x0[dd]);
        const uint64_t xp1 = pk2(x1[dd], x1[dd]);
        #pragma unroll
        for (int k = 0; k < 2; k++) {
            uint64_t z0 = fma2(xp0, A[dd][k], Bv[dd][k]);
            uint64_t z1 = fma2(xp1, A[dd][k], Bv[dd][k]);
            uint64_t w0 = fma2(z0, z0, M1);          // z^2 - 1
            uint64_t w1 = fma2(z1, z1, M1);
            sacc[0][k] = add2(sacc[0][k], w0);       // sum z^2 = sum w + count
            sacc[1][k] = add2(sacc[1][k], w1);
            pacc[0][k] = mul2(pacc[0][k], w0);
            pacc[1][k] = mul2(pacc[1][k], w1);
        }
    }
}

__global__ __launch_bounds__(TPB, 4)
void wavelet_kernel(const float* __restrict__ x,
                    const float* __restrict__ centers,
                    const float* __restrict__ scales,
                    float* __restrict__ out, int N)
{
    float* sx = smem_dyn;                   // [BT][XSTRIDE]  b-major
    float* sa = sx + BT * XSTRIDE;          // [D][ASTRIDE]   d-major (transposed): 1/s
    float* sb = sa + D_DIM * ASTRIDE;       // [D][ASTRIDE]   -c/s

    const int tid = threadIdx.x;
    const int b0 = blockIdx.x * BT;
    const int n0 = blockIdx.y * NT;

    // x tile (coalesced)
    for (int i = tid; i < BT * D_DIM; i += TPB) {
        int r = i >> 6, c = i & 63;
        sx[r * XSTRIDE + c] = x[(b0 + r) * D_DIM + c];
    }
    // a/b tiles, transposed to [d][n]
    #pragma unroll 4
    for (int i = tid; i < NT * D_DIM; i += TPB) {
        int d = i & 63, n = i >> 6;
        int g = (n0 + n) * D_DIM + d;
        float inv = 1.0f / scales[g];
        sa[d * ASTRIDE + n] = inv;
        sb[d * ASTRIDE + n] = -centers[g] * inv;
    }
    __syncthreads();

    const int ng = tid & 15;   // 4 n's at ng*4
    const int bg = tid >> 4;   // 2 b's at bg*2

    const float* xrow = sx + (bg * 2) * XSTRIDE;
    const float* arow = sa + ng * 4;
    const float* brow = sb + ng * 4;

    const uint64_t M1 = pk2(-1.0f, -1.0f);
    uint64_t sacc[2][2], pacc[2][2];
    #pragma unroll
    for (int bi = 0; bi < 2; bi++)
        #pragma unroll
        for (int k = 0; k < 2; k++) { sacc[bi][k] = pk2(0.f, 0.f); pacc[bi][k] = pk2(1.f, 1.f); }

    // first half: d = 0..31
    #pragma unroll 1
    for (int dblk = 0; dblk < 32; dblk += 4)
        do_dblk(xrow, arow, brow, dblk, M1, sacc, pacc);

    // range-control fold: Gaussian factor for first 32 dims
    #pragma unroll
    for (int bi = 0; bi < 2; bi++)
        #pragma unroll
        for (int k = 0; k < 2; k++) {
            float s0, s1, p0, p1;
            upk2(sacc[bi][k], s0, s1);
            upk2(pacc[bi][k], p0, p1);
            p0 *= __expf(-0.5f * (s0 + 32.0f));
            p1 *= __expf(-0.5f * (s1 + 32.0f));
            pacc[bi][k] = pk2(p0, p1);
            sacc[bi][k] = pk2(0.f, 0.f);
        }

    // second half: d = 32..63
    #pragma unroll 1
    for (int dblk = 32; dblk < 64; dblk += 4)
        do_dblk(xrow, arow, brow, dblk, M1, sacc, pacc);

    // epilogue
    float* orow = out + (long)(b0 + bg * 2) * N + n0 + ng * 4;
    #pragma unroll
    for (int bi = 0; bi < 2; bi++) {
        float h[4];
        #pragma unroll
        for (int k = 0; k < 2; k++) {
            float s0, s1, p0, p1;
            upk2(sacc[bi][k], s0, s1);
            upk2(pacc[bi][k], p0, p1);
            h[2 * k]     = p0 * __expf(-0.5f * (s0 + 32.0f));
            h[2 * k + 1] = p1 * __expf(-0.5f * (s1 + 32.0f));
        }
        float4 v = {h[0], h[1], h[2], h[3]};
        *reinterpret_cast<float4*>(orow + (long)bi * N) = v;
    }
}

extern "C" void kernel_launch(void* const* d_in, const int* in_sizes, int n_in,
                              void* d_out, int out_size)
{
    const float* x       = (const float*)d_in[0];
    const float* centers = (const float*)d_in[1];
    const float* scales  = (const float*)d_in[2];
    float* out = (float*)d_out;

    const int B = in_sizes[0] / D_DIM;   // 8192
    const int N = in_sizes[1] / D_DIM;   // 512

    const int smem_bytes = (BT * XSTRIDE + 2 * D_DIM * ASTRIDE) * sizeof(float); // 43520
    static bool attr_set = false;
    if (!attr_set) {
        cudaFuncSetAttribute(wavelet_kernel,
                             cudaFuncAttributeMaxDynamicSharedMemorySize, smem_bytes);
        attr_set = true;
    }

    dim3 grid(B / BT, N / NT);           // (256, 8) = 2048 blocks
    wavelet_kernel<<<grid, TPB, smem_bytes>>>(x, centers, scales, out, N);
}